// round 1
// baseline (speedup 1.0000x reference)
#include <cuda_runtime.h>

#define BB 4
#define NN 4096
#define HH 16
#define DD 64
#define HD (HH*DD)          // 1024
#define BH (BB*HH)          // 64
#define CH 8                // chunks over N for phase-1 parallelism
#define CHTOK (NN/CH)       // 512 tokens per chunk
#define EPSZ 1e-6f

// Scratch (static device globals — no allocation)
__device__ float g_KVpart[CH*BH*DD*DD];   // 8 MB: per-chunk partial K^T V
__device__ float g_KSpart[CH*BH*DD];      // per-chunk partial K column sums
__device__ float g_C[BH*DD*DD];           // folded KV @ W_out_h^T (1 MB)
__device__ float g_Ksum[BH*DD];           // reduced K sums

__device__ __forceinline__ float phi(float x) {
    // elu(x)+1 : x>0 ? x+1 : exp(x)
    return x > 0.0f ? x + 1.0f : __expf(x);
}
__device__ __forceinline__ float4 phi4(float4 v) {
    float4 r; r.x = phi(v.x); r.y = phi(v.y); r.z = phi(v.z); r.w = phi(v.w);
    return r;
}

// ---------------------------------------------------------------------------
// Phase 1: per-(b,h,chunk) partial KV[d][m] = sum_t phi(K[t][d]) * V[t][m]
// 512 blocks, 256 threads, 4x4 register blocking over a 64x64 output.
// ---------------------------------------------------------------------------
__global__ __launch_bounds__(256) void kv_partial_kernel(
    const float* __restrict__ key, const float* __restrict__ value)
{
    __shared__ float Ks[32][68];
    __shared__ float Vs[32][68];

    const int bx  = blockIdx.x;       // 0 .. BH*CH-1
    const int c   = bx % CH;
    const int bh  = bx / CH;
    const int b   = bh / HH;
    const int h   = bh % HH;
    const int tid = threadIdx.x;
    const int ty  = tid >> 4;         // 0..15  (d block)
    const int tx  = tid & 15;         // 0..15  (m block)

    float acc[4][4];
#pragma unroll
    for (int i = 0; i < 4; i++)
#pragma unroll
        for (int j = 0; j < 4; j++) acc[i][j] = 0.0f;
    float ksacc = 0.0f;

    const int n0 = c * CHTOK;

    for (int tile = 0; tile < CHTOK / 32; tile++) {
        const int t0 = n0 + tile * 32;
        // cooperative load: 32 tokens x 64 floats for K (phi applied) and V
#pragma unroll
        for (int i = 0; i < 2; i++) {
            const int lin = tid + i * 256;      // 0..511
            const int t   = lin >> 4;           // 0..31
            const int d4  = (lin & 15) * 4;
            const int row = (b * NN + t0 + t);
            const float4 kq = *(const float4*)(key   + (size_t)row * HD + h * DD + d4);
            const float4 vq = *(const float4*)(value + (size_t)row * HD + h * DD + d4);
            *(float4*)&Ks[t][d4] = phi4(kq);
            *(float4*)&Vs[t][d4] = vq;
        }
        __syncthreads();

        if (tid < 64) {
#pragma unroll
            for (int t = 0; t < 32; t++) ksacc += Ks[t][tid];
        }

#pragma unroll 4
        for (int t = 0; t < 32; t++) {
            const float4 av = *(const float4*)&Ks[t][ty * 4];
            const float4 vv = *(const float4*)&Vs[t][tx * 4];
            float a[4] = {av.x, av.y, av.z, av.w};
            float v[4] = {vv.x, vv.y, vv.z, vv.w};
#pragma unroll
            for (int i = 0; i < 4; i++)
#pragma unroll
                for (int j = 0; j < 4; j++) acc[i][j] += a[i] * v[j];
        }
        __syncthreads();
    }

    float* outp = g_KVpart + (size_t)(c * BH + bh) * DD * DD;
#pragma unroll
    for (int i = 0; i < 4; i++) {
        float4 w = make_float4(acc[i][0], acc[i][1], acc[i][2], acc[i][3]);
        *(float4*)(outp + (ty * 4 + i) * DD + tx * 4) = w;
    }
    if (tid < 64) g_KSpart[(c * BH + bh) * DD + tid] = ksacc;
}

// ---------------------------------------------------------------------------
// Phase 1.5: reduce chunk partials; fold projection:
//   C[bh][d][j] = sum_m KV[bh][d][m] * W_out[j][h*64+m]
// 64 blocks, 256 threads.
// ---------------------------------------------------------------------------
__global__ __launch_bounds__(256) void fold_kernel(const float* __restrict__ W_out)
{
    __shared__ float KVs[DD][68];
    __shared__ float Ws[DD][68];

    const int bh  = blockIdx.x;
    const int h   = bh % HH;
    const int tid = threadIdx.x;
    const int ty  = tid >> 4;
    const int tx  = tid & 15;

    // reduce KV partials into smem
#pragma unroll
    for (int i = 0; i < 4; i++) {
        const int lin = (tid + i * 256) * 4;    // float4 element offset, 0..4092
        float4 s = make_float4(0.f, 0.f, 0.f, 0.f);
#pragma unroll
        for (int cc = 0; cc < CH; cc++) {
            const float4 p = *(const float4*)(g_KVpart + (size_t)(cc * BH + bh) * DD * DD + lin);
            s.x += p.x; s.y += p.y; s.z += p.z; s.w += p.w;
        }
        const int d = lin >> 6, m = lin & 63;
        *(float4*)&KVs[d][m] = s;
    }
    // load W slice: Ws[j][m] = W_out[j*HD + h*64 + m]
#pragma unroll
    for (int i = 0; i < 4; i++) {
        const int lin = (tid + i * 256) * 4;
        const int j = lin >> 6, m = lin & 63;
        *(float4*)&Ws[j][m] = *(const float4*)(W_out + (size_t)j * HD + h * DD + m);
    }
    if (tid < 64) {
        float s = 0.0f;
#pragma unroll
        for (int cc = 0; cc < CH; cc++) s += g_KSpart[(cc * BH + bh) * DD + tid];
        g_Ksum[bh * DD + tid] = s;
    }
    __syncthreads();

    float acc[4][4];
#pragma unroll
    for (int i = 0; i < 4; i++)
#pragma unroll
        for (int j = 0; j < 4; j++) acc[i][j] = 0.0f;

#pragma unroll 4
    for (int m = 0; m < 64; m++) {
        float a[4], w[4];
#pragma unroll
        for (int i = 0; i < 4; i++) a[i] = KVs[ty * 4 + i][m];
#pragma unroll
        for (int j = 0; j < 4; j++) w[j] = Ws[tx * 4 + j][m];
#pragma unroll
        for (int i = 0; i < 4; i++)
#pragma unroll
            for (int j = 0; j < 4; j++) acc[i][j] += a[i] * w[j];
    }

    float* cp = g_C + (size_t)bh * DD * DD;
#pragma unroll
    for (int i = 0; i < 4; i++) {
        float4 w = make_float4(acc[i][0], acc[i][1], acc[i][2], acc[i][3]);
        *(float4*)(cp + (ty * 4 + i) * DD + tx * 4) = w;
    }
}

// ---------------------------------------------------------------------------
// Phase 2: per 64-token tile, accumulate over heads:
//   out[t][j] = b_out[j] + sum_h Z[t,h] * (Qphi[t,h,:] @ C[b,h][:,j])
// Z folded into Qphi rows before the matmul. 256 blocks, 256 threads.
// ---------------------------------------------------------------------------
__global__ __launch_bounds__(256) void out_kernel(
    const float* __restrict__ query, const float* __restrict__ b_out,
    float* __restrict__ out)
{
    __shared__ float Qp[64][68];
    __shared__ float Cs[64][68];
    __shared__ float Ksum_s[DD];

    const int blk = blockIdx.x;                 // 0 .. B*N/64 - 1
    const int b   = blk / (NN / 64);
    const int t0g = blk * 64;                   // global token row start
    const int tid = threadIdx.x;
    const int ty  = tid >> 4;
    const int tx  = tid & 15;

    float acc[4][4];
#pragma unroll
    for (int i = 0; i < 4; i++)
#pragma unroll
        for (int j = 0; j < 4; j++) acc[i][j] = 0.0f;

    for (int h = 0; h < HH; h++) {
        const int bh = b * HH + h;
        if (tid < 64) Ksum_s[tid] = g_Ksum[bh * DD + tid];

        // load Q tile with phi
#pragma unroll
        for (int i = 0; i < 4; i++) {
            const int lin = tid + i * 256;      // 0..1023
            const int t = lin >> 4;
            const int d4 = (lin & 15) * 4;
            const float4 qv = *(const float4*)(query + (size_t)(t0g + t) * HD + h * DD + d4);
            *(float4*)&Qp[t][d4] = phi4(qv);
        }
        // load C tile
#pragma unroll
        for (int i = 0; i < 4; i++) {
            const int lin = tid + i * 256;
            const int t = lin >> 4;
            const int d4 = (lin & 15) * 4;
            *(float4*)&Cs[t][d4] = *(const float4*)(g_C + (size_t)bh * DD * DD + lin * 4);
        }
        __syncthreads();

        // Z and row scaling (64 threads, one token each)
        if (tid < 64) {
            float dot = 0.0f;
#pragma unroll
            for (int d = 0; d < 64; d++) dot += Qp[tid][d] * Ksum_s[d];
            const float z = 1.0f / (dot + EPSZ);
#pragma unroll
            for (int d = 0; d < 64; d++) Qp[tid][d] *= z;
        }
        __syncthreads();

        // acc += Qp(64x64) @ Cs(64x64), 4x4 per thread
#pragma unroll 4
        for (int d = 0; d < 64; d++) {
            float a[4];
#pragma unroll
            for (int i = 0; i < 4; i++) a[i] = Qp[ty * 4 + i][d];
            const float4 cv = *(const float4*)&Cs[d][tx * 4];
            float c[4] = {cv.x, cv.y, cv.z, cv.w};
#pragma unroll
            for (int i = 0; i < 4; i++)
#pragma unroll
                for (int j = 0; j < 4; j++) acc[i][j] += a[i] * c[j];
        }
        __syncthreads();
    }

    const float4 bv = *(const float4*)(b_out + tx * 4);
    const float bj[4] = {bv.x, bv.y, bv.z, bv.w};
#pragma unroll
    for (int i = 0; i < 4; i++) {
        float4 w = make_float4(acc[i][0] + bj[0], acc[i][1] + bj[1],
                               acc[i][2] + bj[2], acc[i][3] + bj[3]);
        *(float4*)(out + (size_t)(t0g + ty * 4 + i) * DD + tx * 4) = w;
    }
}

// ---------------------------------------------------------------------------
extern "C" void kernel_launch(void* const* d_in, const int* in_sizes, int n_in,
                              void* d_out, int out_size)
{
    const float* q  = (const float*)d_in[0];
    const float* k  = (const float*)d_in[1];
    const float* v  = (const float*)d_in[2];
    const float* W  = (const float*)d_in[3];
    const float* bo = (const float*)d_in[4];
    float* out = (float*)d_out;

    kv_partial_kernel<<<BH * CH, 256>>>(k, v);
    fold_kernel<<<BH, 256>>>(W);
    out_kernel<<<(BB * NN) / 64, 256>>>(q, bo, out);
}